// round 17
// baseline (speedup 1.0000x reference)
#include <cuda_runtime.h>
#include <cstdint>

#define BATCH 16
#define TT    1024
#define FF    128
#define RR    2048
#define HALF  1024
#define GAMMA 0.95f

#define NCTA          128
#define ROWS_PER_CTA  16
#define NTHREADS      256
#define CHUNK         512
#define NCHUNK        4

// ---- SMEM layout (floats) ----
#define WPAD   2050
#define SW_FLOATS   (ROWS_PER_CTA * WPAD)              // 32800
#define HROWF(b)    ((b) * 520 + ((b) >> 3) * 8)
#define HBUF_FLOATS 8336
#define SH_FLOATS   (2 * HBUF_FLOATS)                  // 16672
#define SMEM_MAIN   ((SW_FLOATS + SH_FLOATS) * 4)      // 197888 B

#define PPAD   130
#define SMEM_PROJ   ((128 * PPAD + BATCH * PPAD) * 4)  // 74880 B

typedef unsigned long long ull;

// ---------------- device globals ----------------
__device__ float    g_proj[(size_t)TT * BATCH * HALF]; // [t][b][r<HALF]
__device__ float    g_h[2][BATCH * RR];                // ping-pong state
__device__ unsigned g_arrive = 0;                      // monotonic arrive counter
__device__ unsigned g_flag   = 0;                      // monotonic round flag

// ---------------- helpers ----------------
__device__ __forceinline__ ull ffma2(ull a, ull b, ull c) {
    ull d;
    asm("fma.rn.f32x2 %0, %1, %2, %3;" : "=l"(d) : "l"(a), "l"(b), "l"(c));
    return d;
}
__device__ __forceinline__ float lohi_sum(ull v) {
    unsigned lo, hi;
    asm("mov.b64 {%0, %1}, %2;" : "=r"(lo), "=r"(hi) : "l"(v));
    return __uint_as_float(lo) + __uint_as_float(hi);
}
__device__ __forceinline__ void cp_async16(void* smem_dst, const void* gmem_src) {
    unsigned s = (unsigned)__cvta_generic_to_shared(smem_dst);
    asm volatile("cp.async.cg.shared.global [%0], [%1], 16;" :: "r"(s), "l"(gmem_src));
}

// Chip-wide barrier (R14-proven primitives). Only change: nanosleep backoff in
// the poll loop so 127 pollers don't serialize the LTS atomic ALU against the
// release. Monotonic counters -> graph-replay-safe.
__device__ __forceinline__ void grid_barrier() {
    __syncthreads();
    if (threadIdx.x == 0) {
        __threadfence();                                  // release my CTA's writes
        unsigned v = atomicAdd(&g_arrive, 1u);
        unsigned round = v >> 7;                          // global round index
        if ((v & 127u) == 127u) {                         // last arriver
            __threadfence();
            atomicExch(&g_flag, round + 1u);              // broadcast release
        } else {
            while (atomicAdd(&g_flag, 0u) < round + 1u)
                __nanosleep(64);
        }
        __threadfence();                                  // acquire
    }
    __syncthreads();
}

// Stage one 512-k chunk of h (16 batches x 512 floats = 2048 float4).
__device__ __forceinline__ void load_chunk(float* dstbase, const float* hsrc,
                                           int c, int tid) {
#pragma unroll
    for (int it = 0; it < 8; ++it) {
        int e  = tid + it * NTHREADS;   // 0..2047
        int b  = e >> 7;                // 128 float4 per batch row
        int k4 = e & 127;
        cp_async16(dstbase + HROWF(b) + k4 * 4,
                   hsrc + (size_t)b * RR + (size_t)c * CHUNK + k4 * 4);
    }
    asm volatile("cp.async.commit_group;" ::: "memory");
}

// ---------------- kernel 1: masked input projection (proven) ----
__global__ void __launch_bounds__(256, 2)
proj_kernel(const float* __restrict__ inputs, const float* __restrict__ Win) {
    extern __shared__ float smem[];
    float* sWin = smem;                 // [128][PPAD]
    float* sInp = smem + 128 * PPAD;    // [16][PPAD]

    const int tid = threadIdx.x;
    const int j0  = blockIdx.x * 128;
    const int t0  = blockIdx.y * 4;

    for (int i = tid; i < 128 * 32; i += 256) {
        int jr = i >> 5, f4 = i & 31;
        float4 v = *(const float4*)(Win + (size_t)(j0 + jr) * FF + f4 * 4);
        float* d = sWin + jr * PPAD + f4 * 4;
        d[0] = v.x; d[1] = v.y; d[2] = v.z; d[3] = v.w;
    }

    const int j  = tid & 127;
    const int hb = tid >> 7;
    const float* wp = sWin + j * PPAD;

    for (int tt = 0; tt < 4; ++tt) {
        int t = t0 + tt;
        __syncthreads();
        for (int i = tid; i < BATCH * 32; i += 256) {
            int b = i >> 5, f4 = i & 31;
            float4 v = *(const float4*)(inputs + ((size_t)b * TT + t) * FF + f4 * 4);
            float* d = sInp + b * PPAD + f4 * 4;
            d[0] = v.x; d[1] = v.y; d[2] = v.z; d[3] = v.w;
        }
        __syncthreads();

        ull acc[8];
#pragma unroll
        for (int n = 0; n < 8; ++n) acc[n] = 0ull;

#pragma unroll 8
        for (int f = 0; f < FF; f += 2) {
            ull wv = *(const ull*)(wp + f);
#pragma unroll
            for (int jj = 0; jj < 8; ++jj) {
                ull hv = *(const ull*)(sInp + (hb * 8 + jj) * PPAD + f);
                acc[jj] = ffma2(hv, wv, acc[jj]);
            }
        }
#pragma unroll
        for (int jj = 0; jj < 8; ++jj) {
            int b = hb * 8 + jj;
            g_proj[((size_t)t * BATCH + b) * HALF + j0 + j] = lohi_sum(acc[jj]);
        }
    }
}

// ---------------- kernel 2: persistent recurrence ----------------
// CTA c owns rows [c*16, c*16+16). Register tile per thread: 4 rows x 8 batches.
// GEMM decomposition: rg = tid&3, bgp = (tid>>2)&1, ks = tid>>3 (32-way K-split).
__global__ void __launch_bounds__(NTHREADS, 1)
esn_kernel(const float* __restrict__ Wrec, const float* __restrict__ bias,
           const float* __restrict__ rstart, float* __restrict__ out) {
    extern __shared__ float smem[];
    float* sW   = smem;                 // [16][WPAD]
    float* sh   = smem + SW_FLOATS;     // 2 x HBUF_FLOATS
    float* sRed = sh;                   // alias: 256*33 = 8448 <= 16672 floats

    const int tid = threadIdx.x;
    const int cta = blockIdx.x;
    const int rg  = tid & 3;
    const int bgp = (tid >> 2) & 1;
    const int ks  = tid >> 3;
    const int ks2 = ks * 2;

    // One-time W fill
    {
        const float* wsrc = Wrec + (size_t)cta * ROWS_PER_CTA * RR;
        for (int i = tid; i < ROWS_PER_CTA * (RR / 2); i += NTHREADS) {
            int r  = i >> 10;
            int ku = i & 1023;
            *(ull*)(sW + r * WPAD + ku * 2) =
                *(const ull*)(wsrc + (size_t)r * RR + ku * 2);
        }
    }

    // Epilogue mapping (coalesced): consecutive lanes -> consecutive rows.
    const int er = tid & 15;                     // local row 0..15
    const int eb = tid >> 4;                     // batch 0..15
    const int gr = cta * ROWS_PER_CTA + er;
    const int o  = er * 16 + eb;                 // reduction slot (row*16+batch)
    const float bia = bias[gr];

    // h0 = broadcast(reservoir_start)
    g_h[0][eb * RR + gr] = rstart[gr];
    grid_barrier();

    const float* wbase = sW + (rg * 4) * WPAD;
    const int hbase_off = bgp * (8 * 520 + 8);

    for (int t = 0; t < TT; ++t) {
        const float* hc = g_h[t & 1];
        float*       hn = g_h[(t + 1) & 1];

        load_chunk(sh, hc, 0, tid);              // prefetch chunk 0 -> buf 0

        // Early epilogue operand loads (coalesced; hidden under the GEMM)
        const float hold  = hc[eb * RR + gr];
        const float projv = (gr < HALF)
                          ? g_proj[((size_t)t * BATCH + eb) * HALF + gr]
                          : 0.0f;

        ull acc[32];
#pragma unroll
        for (int n = 0; n < 32; ++n) acc[n] = 0ull;

#pragma unroll
        for (int c = 0; c < NCHUNK; ++c) {
            if (c + 1 < NCHUNK) {
                load_chunk(sh + ((c + 1) & 1) * HBUF_FLOATS, hc, c + 1, tid);
                asm volatile("cp.async.wait_group 1;" ::: "memory");
            } else {
                asm volatile("cp.async.wait_group 0;" ::: "memory");
            }
            __syncthreads();

            const float* hb = sh + (c & 1) * HBUF_FLOATS + hbase_off;
            const float* wb = wbase + c * CHUNK;

#pragma unroll
            for (int it = 0; it < 8; ++it) {
                const int kl = it * 64 + ks2;
                ull hv[8], wv[4];
#pragma unroll
                for (int j = 0; j < 8; ++j)
                    hv[j] = *(const ull*)(hb + j * 520 + kl);
#pragma unroll
                for (int i = 0; i < 4; ++i)
                    wv[i] = *(const ull*)(wb + i * WPAD + kl);
#pragma unroll
                for (int i = 0; i < 4; ++i)
#pragma unroll
                    for (int j = 0; j < 8; ++j)
                        acc[i * 8 + j] = ffma2(hv[j], wv[i], acc[i * 8 + j]);
            }
            __syncthreads();
        }

        // K-split partial store: output slot oo = (rg*4+i)*16 + bgp*8 + j.
        // Column swizzled by the writer's rg = oo>>6 -> col = (ks + 4*(oo>>6))&31.
#pragma unroll
        for (int i = 0; i < 4; ++i)
#pragma unroll
            for (int j = 0; j < 8; ++j) {
                int oo = (rg * 4 + i) * 16 + bgp * 8 + j;
                int col = (ks + 4 * rg) & 31;
                sRed[oo * 33 + col] = lohi_sum(acc[i * 8 + j]);
            }
        __syncthreads();

        // Thread sums its slot o (swizzle uses o>>6, matching the writer's rg).
        float z = 0.f;
        {
            const int rgo4 = (o >> 6) * 4;
            const float* rp = sRed + o * 33;
#pragma unroll
            for (int s = 0; s < 32; ++s) z += rp[(s + rgo4) & 31];
        }
        z += bia + projv;

        float hnew = (1.0f - GAMMA) * hold + GAMMA * tanhf(z);
        hn[eb * RR + gr] = hnew;                 // coalesced (er in low bits)
        if (gr >= HALF)
            out[((size_t)eb * TT + t) * HALF + (gr - HALF)] = hnew;  // coalesced

        grid_barrier();               // publish hn chip-wide before next step
    }
}

// ---------------- launch ----------------
extern "C" void kernel_launch(void* const* d_in, const int* in_sizes, int n_in,
                              void* d_out, int out_size) {
    const float* inputs = (const float*)d_in[0];   // [16,1024,128]
    const float* Win    = (const float*)d_in[1];   // [2048,128]
    const float* Wrec   = (const float*)d_in[2];   // [2048,2048]
    const float* bias   = (const float*)d_in[3];   // [2048]
    const float* rstart = (const float*)d_in[4];   // [2048]
    float* out = (float*)d_out;                    // [16,1024,1024]

    cudaFuncSetAttribute(proj_kernel, cudaFuncAttributeMaxDynamicSharedMemorySize,
                         SMEM_PROJ);
    cudaFuncSetAttribute(esn_kernel, cudaFuncAttributeMaxDynamicSharedMemorySize,
                         SMEM_MAIN);

    dim3 pgrid(HALF / 128, TT / 4, 1);   // 8 x 256 blocks
    proj_kernel<<<pgrid, 256, SMEM_PROJ>>>(inputs, Win);

    esn_kernel<<<NCTA, NTHREADS, SMEM_MAIN>>>(Wrec, bias, rstart, out);
}